// round 14
// baseline (speedup 1.0000x reference)
#include <cuda_runtime.h>
#include <cuda_bf16.h>
#include <cstdint>

// Pooling_2D_density_3D: out[b] = sum_k P_k X P_k^T, K=81 one-hot projectors,
// I=16, O=8, J=4, B=16 -> X:(16,1024,1024), out:(16,256,256).
//
// Closed form (verified rel_err ~1.2e-8): each output quad is a sum of 1-4
// gathered input quads. With u = global thread id == linear output float4
// index, the source base (quad units) is a bit-permutation of u with four
// DISJOINT shifted fields:
//   base = ((u&7)<<1) | ((u&0xF8)<<2) | ((u&0x700)<<3) | ((u&0x3F800)<<4)
// and the four source quads sit at CONSTANT offsets from base:
//   B      = base + 0      iff (i_r==i_c && j_r==j_c)   [1/64 threads]
//   C      = base + 1025   iff (i_r==i_c)               [8/64 threads]
//   D      = base + 16400  iff (j_r==j_c)               [8/64 threads]
//   center = base + 17425  always
// 49/64 threads execute only the center load.
//
// Since u = bid*256 + tid, bits 8+ come from bid: the bid half of the
// permutation is warp-uniform (uniform datapath), leaving only 4 thread ops
// before the majority path's single LDG. Store is streaming (.cs): output is
// write-once, keep the input set resident in L2 across graph replays.
//
// FINAL. Two identical-kernel replications (R1/R10: 6.24 vs 8.96 wall;
// R12/R13: 6.21 vs 7.55 profiled) prove machine-state noise dominates all
// structural deltas observed across 13 rounds and 10 distinct structures.
// Traffic is provably minimal (2x sector waste structural, zero read reuse,
// 256-bit loads fetch no extra live bytes); instruction count at floor;
// launch shapes swept. This form holds the best recorded profiled duration.

__device__ __forceinline__ void stcs4(float4* p, float4 v)
{
    asm volatile("st.global.cs.v4.f32 [%0], {%1,%2,%3,%4};"
                 :: "l"(p), "f"(v.x), "f"(v.y), "f"(v.z), "f"(v.w) : "memory");
}

__global__ __launch_bounds__(256, 8)
void pool2d_density_kernel(const float4* __restrict__ xq, float4* __restrict__ oq)
{
    const unsigned tid = threadIdx.x;
    const unsigned bid = blockIdx.x;

    // warp-uniform half of the permutation: u bits 8-17 = bid bits 0-9
    //   (u&0x700)<<3 | (u&0x3F800)<<4  ==  ((bid&7)<<11) | ((bid>>3)<<15)
    const unsigned ubase = ((bid & 7u) << 11) | ((bid >> 3) << 15);

    // per-thread half: u bits 0-7 = tid
    const unsigned tbase = ((tid & 7u) << 1) | ((tid & 0xF8u) << 2);

    const float4* __restrict__ p = xq + (ubase | tbase);

    // center term: always present, issued at minimum depth
    float4 acc = __ldg(p + 17425);

    // match predicates (bid side warp-uniform)
    const bool im = ((bid >> 3) & 7u) == ((tid >> 3) & 7u);
    const bool jm = (bid & 7u) == (tid & 7u);

    if (im) {                                   // C group (8/64 threads)
        float4 v = __ldg(p + 1025);
        if (jm) {                               // B group (1/64 threads)
            float4 w = __ldg(p);
            v.x += w.x; v.y += w.y; v.z += w.z; v.w += w.w;
        }
        acc.x += v.x; acc.y += v.y; acc.z += v.z; acc.w += v.w;
    }
    if (jm) {                                   // D group (8/64 threads)
        float4 v = __ldg(p + 16400);
        acc.x += v.x; acc.y += v.y; acc.z += v.z; acc.w += v.w;
    }

    // store address == u (linear): fully coalesced 128B streaming stores
    stcs4(oq + (bid * 256u + tid), acc);
}

extern "C" void kernel_launch(void* const* d_in, const int* in_sizes, int n_in,
                              void* d_out, int out_size)
{
    const float4* x = (const float4*)d_in[0];   // (16, 1024, 1024) fp32 as quads
    float4* out = (float4*)d_out;               // (16, 256, 256) fp32 as quads

    // 262144 output quads, 1 per thread: 1024 blocks x 256 threads
    // (~7 blocks/SM, single wave).
    pool2d_density_kernel<<<1024, 256>>>(x, out);
}

// round 15
// speedup vs baseline: 1.2444x; 1.2444x over previous
#include <cuda_runtime.h>
#include <cuda_bf16.h>
#include <cstdint>

// Pooling_2D_density_3D: out[b] = sum_k P_k X P_k^T, K=81 one-hot projectors,
// I=16, O=8, J=4, B=16 -> X:(16,1024,1024), out:(16,256,256).
//
// Closed form (verified rel_err ~1.2e-8): each output quad is a sum of 1-4
// gathered input quads. With u = global thread id == linear output float4
// index, the source base (quad units) is a bit-permutation of u with four
// DISJOINT shifted fields:
//   base = ((u&7)<<1) | ((u&0xF8)<<2) | ((u&0x700)<<3) | ((u&0x3F800)<<4)
// and the four source quads sit at CONSTANT offsets from base:
//   B      = base + 0      iff (i_r==i_c && j_r==j_c)   [1/64 threads]
//   C      = base + 1025   iff (i_r==i_c)               [8/64 threads]
//   D      = base + 16400  iff (j_r==j_c)               [8/64 threads]
//   center = base + 17425  always
// 49/64 threads execute only the center load (~15 dynamic instructions).
//
// Since u = bid*256 + tid, bits 8+ come from bid: the bid half of the
// permutation is warp-uniform (uniform datapath), leaving only 4 thread ops
// before the majority path's single LDG.
//
// Round-14 A/B: default store (the 6.24us wall record used a plain STG;
// .cs drew 6.59/8.96/8.96 across three identical runs — unproven benefit,
// possible store-ack latency cost, and L2 pollution was never a real risk
// at 4MB output vs 126MB L2). Everything else identical to the converged
// form. Three identical-kernel replications prove +/-1.5us machine-state
// noise dominates all structural deltas; traffic/instruction count are at
// their provable floors.

__global__ __launch_bounds__(256, 8)
void pool2d_density_kernel(const float4* __restrict__ xq, float4* __restrict__ oq)
{
    const unsigned tid = threadIdx.x;
    const unsigned bid = blockIdx.x;

    // warp-uniform half of the permutation: u bits 8-17 = bid bits 0-9
    //   (u&0x700)<<3 | (u&0x3F800)<<4  ==  ((bid&7)<<11) | ((bid>>3)<<15)
    const unsigned ubase = ((bid & 7u) << 11) | ((bid >> 3) << 15);

    // per-thread half: u bits 0-7 = tid
    const unsigned tbase = ((tid & 7u) << 1) | ((tid & 0xF8u) << 2);

    const float4* __restrict__ p = xq + (ubase | tbase);

    // center term: always present, issued at minimum depth
    float4 acc = __ldg(p + 17425);

    // match predicates (bid side warp-uniform)
    const bool im = ((bid >> 3) & 7u) == ((tid >> 3) & 7u);
    const bool jm = (bid & 7u) == (tid & 7u);

    if (im) {                                   // C group (8/64 threads)
        float4 v = __ldg(p + 1025);
        if (jm) {                               // B group (1/64 threads)
            float4 w = __ldg(p);
            v.x += w.x; v.y += w.y; v.z += w.z; v.w += w.w;
        }
        acc.x += v.x; acc.y += v.y; acc.z += v.z; acc.w += v.w;
    }
    if (jm) {                                   // D group (8/64 threads)
        float4 v = __ldg(p + 16400);
        acc.x += v.x; acc.y += v.y; acc.z += v.z; acc.w += v.w;
    }

    // store address == u (linear): fully coalesced 128B stores per warp
    oq[bid * 256u + tid] = acc;
}

extern "C" void kernel_launch(void* const* d_in, const int* in_sizes, int n_in,
                              void* d_out, int out_size)
{
    const float4* x = (const float4*)d_in[0];   // (16, 1024, 1024) fp32 as quads
    float4* out = (float4*)d_out;               // (16, 256, 256) fp32 as quads

    // 262144 output quads, 1 per thread: 1024 blocks x 256 threads
    // (~7 blocks/SM, single wave).
    pool2d_density_kernel<<<1024, 256>>>(x, out);
}

// round 16
// speedup vs baseline: 1.3527x; 1.0870x over previous
#include <cuda_runtime.h>
#include <cuda_bf16.h>
#include <cstdint>

// Pooling_2D_density_3D: out[b] = sum_k P_k X P_k^T, K=81 one-hot projectors,
// I=16, O=8, J=4, B=16 -> X:(16,1024,1024), out:(16,256,256).
//
// Closed form (verified rel_err ~1.2e-8): each output quad is a sum of 1-4
// gathered input quads. With u = global thread id == linear output float4
// index, the source base (quad units) is a bit-permutation of u with four
// DISJOINT shifted fields:
//   base = ((u&7)<<1) | ((u&0xF8)<<2) | ((u&0x700)<<3) | ((u&0x3F800)<<4)
// and the four source quads sit at CONSTANT offsets from base:
//   B      = base + 0      iff (i_r==i_c && j_r==j_c)   [1/64 threads]
//   C      = base + 1025   iff (i_r==i_c)               [8/64 threads]
//   D      = base + 16400  iff (j_r==j_c)               [8/64 threads]
//   center = base + 17425  always
// 49/64 threads execute only the center load (~15 dynamic instructions).
//
// Since u = bid*256 + tid, bits 8+ come from bid: the bid half of the
// permutation is warp-uniform (uniform datapath), leaving only 4 thread ops
// before the majority path's single LDG. Store address == u, so warp stores
// are fully coalesced 128B transactions with zero address math.
//
// FINAL — converged after 15 rounds. Evidence: 10 distinct structures
// (MLP scaling, branch-free masked FMA, unconditional loads, f32x2 packing,
// ch-pair amortization, grid shapes 512x128..2048x128, .cs stores) all land
// in 6.2-9.0us, while 5 replications of identical binaries span that same
// range (6.24 vs 8.96; 6.21 vs 7.55 profiled): machine-state noise dominates
// every structural delta. Traffic is provably minimal (the 2x sector waste is
// structural — no needed quad shares a 32B sector with another needed quad;
// reads have zero reuse; 256-bit loads fetch no extra live bytes). The
// session's real win is the Round-1 closed-form rewrite of the 81-projector
// masked gather into 1-4 loads per output element.

__global__ __launch_bounds__(256, 8)
void pool2d_density_kernel(const float4* __restrict__ xq, float4* __restrict__ oq)
{
    const unsigned tid = threadIdx.x;
    const unsigned bid = blockIdx.x;

    // warp-uniform half of the permutation: u bits 8-17 = bid bits 0-9
    //   (u&0x700)<<3 | (u&0x3F800)<<4  ==  ((bid&7)<<11) | ((bid>>3)<<15)
    const unsigned ubase = ((bid & 7u) << 11) | ((bid >> 3) << 15);

    // per-thread half: u bits 0-7 = tid
    const unsigned tbase = ((tid & 7u) << 1) | ((tid & 0xF8u) << 2);

    const float4* __restrict__ p = xq + (ubase | tbase);

    // center term: always present, issued at minimum depth
    float4 acc = __ldg(p + 17425);

    // match predicates (bid side warp-uniform)
    const bool im = ((bid >> 3) & 7u) == ((tid >> 3) & 7u);
    const bool jm = (bid & 7u) == (tid & 7u);

    if (im) {                                   // C group (8/64 threads)
        float4 v = __ldg(p + 1025);
        if (jm) {                               // B group (1/64 threads)
            float4 w = __ldg(p);
            v.x += w.x; v.y += w.y; v.z += w.z; v.w += w.w;
        }
        acc.x += v.x; acc.y += v.y; acc.z += v.z; acc.w += v.w;
    }
    if (jm) {                                   // D group (8/64 threads)
        float4 v = __ldg(p + 16400);
        acc.x += v.x; acc.y += v.y; acc.z += v.z; acc.w += v.w;
    }

    // store address == u (linear): fully coalesced 128B stores per warp
    oq[bid * 256u + tid] = acc;
}

extern "C" void kernel_launch(void* const* d_in, const int* in_sizes, int n_in,
                              void* d_out, int out_size)
{
    const float4* x = (const float4*)d_in[0];   // (16, 1024, 1024) fp32 as quads
    float4* out = (float4*)d_out;               // (16, 256, 256) fp32 as quads

    // 262144 output quads, 1 per thread: 1024 blocks x 256 threads
    // (~7 blocks/SM, single wave).
    pool2d_density_kernel<<<1024, 256>>>(x, out);
}